// round 8
// baseline (speedup 1.0000x reference)
#include <cuda_runtime.h>
#include <cuda_fp16.h>
#include <cstdint>
#include <math.h>

#define NMAX 100000

// ---------------- device scratch ----------------
__device__ float g_norm2[NMAX];
__device__ float g_hmsg[(size_t)NMAX * 64];
// fp16 weights: wih0[256x128] | whh0[256x64] | wih1 | whh1 | wih2 | whh2 (each 256x64)
__device__ __align__(16) __half g_w16[114688];

// ---------------- helpers ----------------
__device__ __forceinline__ void mma16(float* c, const unsigned* a, unsigned b0, unsigned b1) {
    asm volatile(
        "mma.sync.aligned.m16n8k16.row.col.f32.f16.f16.f32 "
        "{%0,%1,%2,%3}, {%4,%5,%6,%7}, {%8,%9}, {%0,%1,%2,%3};\n"
        : "+f"(c[0]), "+f"(c[1]), "+f"(c[2]), "+f"(c[3])
        : "r"(a[0]), "r"(a[1]), "r"(a[2]), "r"(a[3]), "r"(b0), "r"(b1));
}
__device__ __forceinline__ void ldm_x4(unsigned* r, uint32_t addr) {
    asm volatile("ldmatrix.sync.aligned.m8n8.x4.shared.b16 {%0,%1,%2,%3}, [%4];"
                 : "=r"(r[0]), "=r"(r[1]), "=r"(r[2]), "=r"(r[3]) : "r"(addr));
}
__device__ __forceinline__ float tanha(float x) {
    float y;
    asm("tanh.approx.f32 %0, %1;" : "=f"(y) : "f"(x));
    return y;
}
__device__ __forceinline__ float fsig(float x) {          // sigmoid via 1-MUFU tanh
    return fmaf(0.5f, tanha(0.5f * x), 0.5f);
}
__device__ __forceinline__ float ftanh(float x) {         // accurate: 1 - 2/(1+e^{2x})
    float e = __expf(2.0f * x);                            // FMUL + EX2
    float r = __frcp_rn(1.0f + e);                         // FADD + RCP (refined)
    return fmaf(-2.0f, r, 1.0f);
}
__device__ __forceinline__ uint32_t smem_u32(const void* p) {
    uint32_t a;
    asm("{ .reg .u64 t; cvta.to.shared.u64 t, %1; cvt.u32.u64 %0, t; }" : "=r"(a) : "l"(p));
    return a;
}
__device__ __forceinline__ void cp16(uint32_t dst, const void* src) {
    asm volatile("cp.async.ca.shared.global [%0], [%1], 16;" :: "r"(dst), "l"(src) : "memory");
}
__device__ __forceinline__ void cp_commit() { asm volatile("cp.async.commit_group;" ::: "memory"); }
__device__ __forceinline__ void cp_wait1()  { asm volatile("cp.async.wait_group 1;" ::: "memory"); }
__device__ __forceinline__ void cp_wait0()  { asm volatile("cp.async.wait_group 0;" ::: "memory"); }
__device__ __forceinline__ unsigned h2u(__half2 h) { return *(unsigned*)&h; }

// ---------------- SMEM layout (bytes) ----------------
// A:    128 rows x 200 halves (stride 400B) -> 51200
// B:    3 buffers x (128 rows x 40 halves = 80B) -> 3 x 10240
// bsum: 256 floats -> 1024
// Hst:  128 rows x 17 words -> 8704   (pass-0 h stash, fp16 pairs)
#define A_OFF     0
#define B_OFF     51200
#define BBUF_SZ   10240
#define BSUM_OFF  (B_OFF + 3 * BBUF_SZ)        // 81920
#define HST_OFF   (BSUM_OFF + 1024)            // 82944
#define SMEM_BYTES (HST_OFF + 8704)            // 91648

// fp16 weight offsets (in halves): {wih0, whh0, wih1, whh1, wih2, whh2}
__constant__ int c_woff[6] = {0, 32768, 49152, 65536, 81920, 98304};

// ---------------- kernel 0: convert all weights to fp16 ----------------
__global__ void wconv_kernel(const float* __restrict__ wih0, const float* __restrict__ whh0,
                             const float* __restrict__ wih1, const float* __restrict__ whh1,
                             const float* __restrict__ wih2, const float* __restrict__ whh2) {
    int i = blockIdx.x * blockDim.x + threadIdx.x;   // one float2 per thread
    if (i >= 57344) return;
    const float* srcs[6] = {wih0, whh0, wih1, whh1, wih2, whh2};
    int reg, off2;
    if (i < 16384) { reg = 0; off2 = i; }
    else { int t = i - 16384; reg = 1 + t / 8192; off2 = t - (reg - 1) * 8192; }
    float2 v = ((const float2*)srcs[reg])[off2];
    int base2 = (reg == 0) ? 0 : (16384 + (reg - 1) * 8192);
    ((__half2*)g_w16)[base2 + off2] = __floats2half2_rn(v.x, v.y);
}

// ---------------- kernel 1: per-row squared norms (16 lanes/row, float4) ----------------
__global__ void norm2_kernel(const float* __restrict__ feat, int n) {
    int row = (blockIdx.x * blockDim.x + threadIdx.x) >> 4;
    int sl = threadIdx.x & 15;
    if (row >= n) return;
    float4 v = *(const float4*)(feat + (size_t)row * 64 + sl * 4);
    float s = v.x * v.x + v.y * v.y + v.z * v.z + v.w * v.w;
    #pragma unroll
    for (int o = 8; o; o >>= 1) s += __shfl_down_sync(0xffffffffu, s, o, 16);
    if (sl == 0) g_norm2[row] = s;
}

// ---------------- kernel 2: argmax over neighbors + row gather ----------------
__global__ void gather_kernel(const float* __restrict__ feat, const int* __restrict__ src, int n) {
    int w = (blockIdx.x * blockDim.x + threadIdx.x) >> 5;
    int lane = threadIdx.x & 31;
    if (w >= n) return;
    int s = src[(size_t)w * 32 + lane];
    float bv = g_norm2[s];
    int bj = lane;
    #pragma unroll
    for (int o = 16; o; o >>= 1) {
        float ov = __shfl_down_sync(0xffffffffu, bv, o);
        int oj = __shfl_down_sync(0xffffffffu, bj, o);
        if (ov > bv || (ov == bv && oj < bj)) { bv = ov; bj = oj; }
    }
    bj = __shfl_sync(0xffffffffu, bj, 0);
    int bs = __shfl_sync(0xffffffffu, s, bj);
    float2 v = *(const float2*)(feat + (size_t)bs * 64 + lane * 2);
    *(float2*)(g_hmsg + (size_t)w * 64 + lane * 2) = v;
}

// ---------------- kernel 3: fused 3-layer LSTM (fp16 mma + ldmatrix, N-split) ----------------
__global__ __launch_bounds__(256, 2) void lstm_kernel(
    const float* __restrict__ feature,
    const float* __restrict__ h0, const float* __restrict__ c0,
    const float* __restrict__ bih0, const float* __restrict__ bhh0,
    const float* __restrict__ bih1, const float* __restrict__ bhh1,
    const float* __restrict__ bih2, const float* __restrict__ bhh2,
    float* __restrict__ out, int n)
{
    extern __shared__ char smem[];
    unsigned* Xw = (unsigned*)(smem + A_OFF);       // A as 32-bit words (2 halves each)
    float* bsum = (float*)(smem + BSUM_OFF);
    unsigned* Hst = (unsigned*)(smem + HST_OFF);    // pass-0 h stash, stride 17 words
    const uint32_t sbase = smem_u32(smem);

    const int tid = threadIdx.x;
    const int lane = tid & 31;
    const int warp = tid >> 5;
    const int wm = warp >> 1, wn = warp & 1;
    const int gid = lane >> 2, tig = lane & 3;
    const int m0w = wm * 32;
    const int m0 = blockIdx.x * 128;

    // ldmatrix per-lane address offsets
    const uint32_t aLane = (uint32_t)(((lane & 7) + ((lane >> 3) & 1) * 8) * 400 + (lane >> 4) * 16);
    const uint32_t bLane = (uint32_t)(((lane & 7) + (lane >> 4) * 8) * 80 + ((lane >> 3) & 1) * 16);
    const uint32_t aBase0 = sbase + A_OFF + (uint32_t)(m0w * 400) + aLane;          // mf=0
    const uint32_t aBase1 = aBase0 + 16 * 400;                                       // mf=1
    const uint32_t bWn = (uint32_t)(wn * 16 * 80) + bLane;

    // staging role: thread -> (row, 32B half of 64B row)
    const int rp = tid >> 1;
    const int part = tid & 1;
    const int gP0 = (rp >> 5) * 64 + (rp & 31);     // global W row for pass 0
    const uint32_t bdst_local = (uint32_t)(rp * 80 + part * 32);

    const float* bihA[3] = {bih0, bih1, bih2};
    const float* bhhA[3] = {bhh0, bhh1, bhh2};
    const size_t nd = (size_t)n * 64;
    float* out_hs = out + nd;
    float* out_cs = out + 4 * nd;

    // ---- hoisted prologue: stage (l=0,p=0) chunks 0,1 ----
    {
        const __half* s0 = g_w16 + (size_t)gP0 * 128 + part * 16;
        uint32_t d0 = sbase + B_OFF + bdst_local;
        cp16(d0, s0); cp16(d0 + 16, s0 + 8);
        cp_commit();
        const __half* s1 = s0 + 32;
        uint32_t d1 = sbase + B_OFF + BBUF_SZ + bdst_local;
        cp16(d1, s1); cp16(d1 + 16, s1 + 8);
        cp_commit();
    }

    // ---- stage A for layer 0: [hmsg | feature | h0[0]], K=192, fp16 ----
    #pragma unroll 4
    for (int i = 0; i < 24; i++) {
        int idx = tid + (i << 8);
        int m = idx / 48, k4 = idx - m * 48;
        int node = m0 + m;
        float4 v = make_float4(0.f, 0.f, 0.f, 0.f);
        if (node < n) {
            size_t off = (size_t)node * 64;
            if (k4 < 16)      v = *(const float4*)(g_hmsg + off + k4 * 4);
            else if (k4 < 32) v = *(const float4*)(feature + off + (k4 - 16) * 4);
            else              v = *(const float4*)(h0 + off + (k4 - 32) * 4);
        }
        uint2 t;
        t.x = h2u(__floats2half2_rn(v.x, v.y));
        t.y = h2u(__floats2half2_rn(v.z, v.w));
        *(uint2*)(&Xw[m * 100 + k4 * 2]) = t;
    }

    for (int l = 0; l < 3; l++) {
        bsum[tid] = bihA[l][tid] + bhhA[l][tid];
        const int ncg = (l == 0) ? 6 : 4;

        for (int p = 0; p < 2; p++) {
            const int grow = gP0 + p * 32;

            if (!(l == 0 && p == 0)) {
                #pragma unroll 1
                for (int c = 0; c < 2; c++) {
                    const __half* wp; int rs, ko;
                    if (l == 0) { wp = g_w16 + c_woff[0]; rs = 128; ko = c * 32; }
                    else {
                        int reg = (c < 2) ? (2 * l) : (2 * l + 1);
                        wp = g_w16 + c_woff[reg]; rs = 64; ko = (c & 1) * 32;
                    }
                    const __half* src = wp + (size_t)grow * rs + ko + part * 16;
                    uint32_t dst = sbase + B_OFF + (c % 3) * BBUF_SZ + bdst_local;
                    cp16(dst, src); cp16(dst + 16, src + 8);
                    cp_commit();
                }
            }

            float acc[2][8][4];
            #pragma unroll
            for (int mf = 0; mf < 2; mf++)
                #pragma unroll
                for (int f = 0; f < 8; f++)
                    #pragma unroll
                    for (int q = 0; q < 4; q++) acc[mf][f][q] = 0.f;

            #pragma unroll 1
            for (int c = 0; c < ncg; c++) {
                if (c < ncg - 1) cp_wait1(); else cp_wait0();
                __syncthreads();

                const uint32_t bBuf = sbase + B_OFF + (uint32_t)((c % 3) * BBUF_SZ) + bWn;
                const uint32_t aChunk = (uint32_t)(c * 64);       // c*16 words * 4B
                #pragma unroll
                for (int ks = 0; ks < 2; ks++) {
                    unsigned a[2][4];
                    ldm_x4(a[0], aBase0 + aChunk + ks * 32);
                    ldm_x4(a[1], aBase1 + aChunk + ks * 32);
                    #pragma unroll
                    for (int g = 0; g < 4; g++) {
                        unsigned bq[4];
                        ldm_x4(bq, bBuf + (uint32_t)(g * 32 * 80 + ks * 32));
                        mma16(acc[0][2 * g],     a[0], bq[0], bq[1]);
                        mma16(acc[1][2 * g],     a[1], bq[0], bq[1]);
                        mma16(acc[0][2 * g + 1], a[0], bq[2], bq[3]);
                        mma16(acc[1][2 * g + 1], a[1], bq[2], bq[3]);
                    }
                }
                // stage chunk c+2 into buffer (c+2)%3 — never the one being read
                int c2 = c + 2;
                if (c2 < ncg) {
                    const __half* wp; int rs, ko;
                    if (l == 0) {
                        if (c2 < 4) { wp = g_w16 + c_woff[0]; rs = 128; ko = c2 * 32; }
                        else        { wp = g_w16 + c_woff[1]; rs = 64;  ko = (c2 - 4) * 32; }
                    } else {
                        int reg = (c2 < 2) ? (2 * l) : (2 * l + 1);
                        wp = g_w16 + c_woff[reg]; rs = 64; ko = (c2 & 1) * 32;
                    }
                    const __half* src = wp + (size_t)grow * rs + ko + part * 16;
                    uint32_t dst = sbase + B_OFF + (c2 % 3) * BBUF_SZ + bdst_local;
                    cp16(dst, src); cp16(dst + 16, src + 8);
                    cp_commit();
                }
            }
            __syncthreads();   // all MMAs done before epilogue touches Xw/Hst

            // ---------------- epilogue for this pass ----------------
            {
                const float* cg = c0 + (size_t)l * nd;
                const float* h0n = h0 + (size_t)(l + 1) * nd;
                float* hs_l = out_hs + (size_t)l * nd;
                float* cs_l = out_cs + (size_t)l * nd;
                const int cw = wn * 8 + 0;   // stash word base (jf*4 + tig added below)

                #pragma unroll
                for (int mf = 0; mf < 2; mf++)
                    #pragma unroll
                    for (int jf = 0; jf < 2; jf++) {
                        const int d0 = p * 32 + wn * 16 + jf * 8 + 2 * tig;
                        const int sw = cw + jf * 4 + tig;          // stash col word
                        #pragma unroll
                        for (int rh = 0; rh < 2; rh++) {
                            const int row = m0w + mf * 16 + gid + rh * 8;
                            const int node = m0 + row;
                            const bool valid = node < n;
                            const size_t noff = (size_t)node * 64;
                            float2 cp2 = make_float2(0.f, 0.f);
                            if (valid) cp2 = *(const float2*)(cg + noff + d0);
                            float hv[2], cv[2];
                            #pragma unroll
                            for (int q = 0; q < 2; q++) {
                                const int pp = rh * 2 + q;
                                const int d = d0 + q;
                                float iv = acc[mf][0 + jf][pp] + bsum[d];
                                float fv = acc[mf][2 + jf][pp] + bsum[64 + d];
                                float gv = acc[mf][4 + jf][pp] + bsum[128 + d];
                                float ov = acc[mf][6 + jf][pp] + bsum[192 + d];
                                float cprev = q ? cp2.y : cp2.x;
                                float cn = fsig(fv) * cprev + fsig(iv) * ftanh(gv);
                                hv[q] = fsig(ov) * ftanh(cn);
                                cv[q] = cn;
                            }
                            if (valid) {
                                *(float2*)(hs_l + noff + d0) = make_float2(hv[0], hv[1]);
                                *(float2*)(cs_l + noff + d0) = make_float2(cv[0], cv[1]);
                                if (l == 2) *(float2*)(out + noff + d0) = make_float2(hv[0], hv[1]);
                            }
                            if (l < 2) {
                                unsigned hp16 = h2u(__floats2half2_rn(hv[0], hv[1]));
                                if (p == 0) {
                                    Hst[row * 17 + sw] = hp16;     // stash for pass-1 A rebuild
                                } else {
                                    // pass-1 cols: own h + h0[l+1]
                                    Xw[row * 100 + (d0 >> 1)] = hp16;
                                    float2 hh = make_float2(0.f, 0.f);
                                    if (valid) hh = *(const float2*)(h0n + noff + d0);
                                    Xw[row * 100 + 32 + (d0 >> 1)] = h2u(__floats2half2_rn(hh.x, hh.y));
                                    // pass-0 cols: h from smem stash (already fp16), h0 from global
                                    const int dp = d0 - 32;
                                    Xw[row * 100 + (dp >> 1)] = Hst[row * 17 + sw];
                                    float2 h2v = make_float2(0.f, 0.f);
                                    if (valid) h2v = *(const float2*)(h0n + noff + dp);
                                    Xw[row * 100 + 32 + (dp >> 1)] = h2u(__floats2half2_rn(h2v.x, h2v.y));
                                }
                            }
                        }
                    }
                if (p == 1) __syncthreads();   // Xw writes visible before next layer's MMAs
            }
        }
    }
}

// ---------------- launch ----------------
extern "C" void kernel_launch(void* const* d_in, const int* in_sizes, int n_in,
                              void* d_out, int out_size) {
    const float* feature = (const float*)d_in[0];
    const int* src       = (const int*)d_in[1];
    const float* h0      = (const float*)d_in[2];
    const float* c0      = (const float*)d_in[3];
    const float* wih0    = (const float*)d_in[4];
    const float* whh0    = (const float*)d_in[5];
    const float* bih0    = (const float*)d_in[6];
    const float* bhh0    = (const float*)d_in[7];
    const float* wih1    = (const float*)d_in[8];
    const float* whh1    = (const float*)d_in[9];
    const float* bih1    = (const float*)d_in[10];
    const float* bhh1    = (const float*)d_in[11];
    const float* wih2    = (const float*)d_in[12];
    const float* whh2    = (const float*)d_in[13];
    const float* bih2    = (const float*)d_in[14];
    const float* bhh2    = (const float*)d_in[15];
    float* out = (float*)d_out;

    int n = in_sizes[0] / 64;

    cudaFuncSetAttribute(lstm_kernel, cudaFuncAttributeMaxDynamicSharedMemorySize, SMEM_BYTES);

    wconv_kernel<<<224, 256>>>(wih0, whh0, wih1, whh1, wih2, whh2);

    int nblocks = (n * 16 + 255) / 256;
    norm2_kernel<<<nblocks, 256>>>(feature, n);
    int wblocks = (n + 7) / 8;
    gather_kernel<<<wblocks, 256>>>(feature, src, n);

    int lblocks = (n + 127) / 128;
    lstm_kernel<<<lblocks, 256, SMEM_BYTES>>>(
        feature, h0, c0,
        bih0, bhh0, bih1, bhh1, bih2, bhh2,
        out, n);
}

// round 9
// speedup vs baseline: 1.1191x; 1.1191x over previous
#include <cuda_runtime.h>
#include <cuda_fp16.h>
#include <cstdint>
#include <math.h>

#define NMAX 100000

// ---------------- device scratch ----------------
__device__ float g_norm2[NMAX];
__device__ float g_hmsg[(size_t)NMAX * 64];
// fp16 weights: wih0[256x128] | whh0[256x64] | wih1 | whh1 | wih2 | whh2 (each 256x64)
__device__ __align__(16) __half g_w16[114688];

// ---------------- helpers ----------------
__device__ __forceinline__ void mma16(float* c, const unsigned* a, unsigned b0, unsigned b1) {
    asm volatile(
        "mma.sync.aligned.m16n8k16.row.col.f32.f16.f16.f32 "
        "{%0,%1,%2,%3}, {%4,%5,%6,%7}, {%8,%9}, {%0,%1,%2,%3};\n"
        : "+f"(c[0]), "+f"(c[1]), "+f"(c[2]), "+f"(c[3])
        : "r"(a[0]), "r"(a[1]), "r"(a[2]), "r"(a[3]), "r"(b0), "r"(b1));
}
__device__ __forceinline__ float tanha(float x) {
    float y;
    asm("tanh.approx.f32 %0, %1;" : "=f"(y) : "f"(x));
    return y;
}
__device__ __forceinline__ float fsig(float x) {          // sigmoid via 1-MUFU tanh
    return fmaf(0.5f, tanha(0.5f * x), 0.5f);
}
__device__ __forceinline__ float ftanh(float x) {         // accurate tanh (exp-based)
    float a = fabsf(x);
    float e = __expf(-2.0f * a);
    float t = __fdividef(1.0f - e, 1.0f + e);
    return copysignf(t, x);
}
__device__ __forceinline__ uint32_t smem_u32(const void* p) {
    uint32_t a;
    asm("{ .reg .u64 t; cvta.to.shared.u64 t, %1; cvt.u32.u64 %0, t; }" : "=r"(a) : "l"(p));
    return a;
}
__device__ __forceinline__ void cp16(uint32_t dst, const void* src) {
    asm volatile("cp.async.ca.shared.global [%0], [%1], 16;" :: "r"(dst), "l"(src) : "memory");
}
__device__ __forceinline__ void cp_commit() { asm volatile("cp.async.commit_group;" ::: "memory"); }
__device__ __forceinline__ void cp_wait1()  { asm volatile("cp.async.wait_group 1;" ::: "memory"); }
__device__ __forceinline__ void cp_wait0()  { asm volatile("cp.async.wait_group 0;" ::: "memory"); }
__device__ __forceinline__ unsigned h2u(__half2 h) { return *(unsigned*)&h; }

// ---------------- SMEM layout (bytes) ----------------
// A:    128 rows x 200 halves (stride 400B) -> 51200
// B:    3 buffers x (128 rows x 40 halves = 80B) -> 3 x 10240 = 30720
// bsum: 256 floats -> 1024
// Hst:  128 rows x 17 words -> 8704   (pass-0 h stash, fp16 pairs)
// Cs:   128 rows x 36 floats -> 18432 (prefetched c0 slice for current pass)
#define A_OFF     0
#define B_OFF     51200
#define BBUF_SZ   10240
#define BSUM_OFF  (B_OFF + 3 * BBUF_SZ)        // 81920
#define HST_OFF   (BSUM_OFF + 1024)            // 82944
#define CS_OFF    (HST_OFF + 8704)             // 91648
#define SMEM_BYTES (CS_OFF + 18432)            // 110080

// fp16 weight offsets (in halves): {wih0, whh0, wih1, whh1, wih2, whh2}
__constant__ int c_woff[6] = {0, 32768, 49152, 65536, 81920, 98304};

// ---------------- kernel 0: convert all weights to fp16 ----------------
__global__ void wconv_kernel(const float* __restrict__ wih0, const float* __restrict__ whh0,
                             const float* __restrict__ wih1, const float* __restrict__ whh1,
                             const float* __restrict__ wih2, const float* __restrict__ whh2) {
    int i = blockIdx.x * blockDim.x + threadIdx.x;   // one float2 per thread
    if (i >= 57344) return;
    const float* srcs[6] = {wih0, whh0, wih1, whh1, wih2, whh2};
    int reg, off2;
    if (i < 16384) { reg = 0; off2 = i; }
    else { int t = i - 16384; reg = 1 + t / 8192; off2 = t - (reg - 1) * 8192; }
    float2 v = ((const float2*)srcs[reg])[off2];
    int base2 = (reg == 0) ? 0 : (16384 + (reg - 1) * 8192);
    ((__half2*)g_w16)[base2 + off2] = __floats2half2_rn(v.x, v.y);
}

// ---------------- kernel 1: per-row squared norms (16 lanes/row, float4) ----------------
__global__ void norm2_kernel(const float* __restrict__ feat, int n) {
    int row = (blockIdx.x * blockDim.x + threadIdx.x) >> 4;
    int sl = threadIdx.x & 15;
    if (row >= n) return;
    float4 v = *(const float4*)(feat + (size_t)row * 64 + sl * 4);
    float s = v.x * v.x + v.y * v.y + v.z * v.z + v.w * v.w;
    #pragma unroll
    for (int o = 8; o; o >>= 1) s += __shfl_down_sync(0xffffffffu, s, o, 16);
    if (sl == 0) g_norm2[row] = s;
}

// ---------------- kernel 2: argmax over neighbors + row gather ----------------
__global__ void gather_kernel(const float* __restrict__ feat, const int* __restrict__ src, int n) {
    int w = (blockIdx.x * blockDim.x + threadIdx.x) >> 5;
    int lane = threadIdx.x & 31;
    if (w >= n) return;
    int s = src[(size_t)w * 32 + lane];
    float bv = g_norm2[s];
    int bj = lane;
    #pragma unroll
    for (int o = 16; o; o >>= 1) {
        float ov = __shfl_down_sync(0xffffffffu, bv, o);
        int oj = __shfl_down_sync(0xffffffffu, bj, o);
        if (ov > bv || (ov == bv && oj < bj)) { bv = ov; bj = oj; }
    }
    bj = __shfl_sync(0xffffffffu, bj, 0);
    int bs = __shfl_sync(0xffffffffu, s, bj);
    float2 v = *(const float2*)(feat + (size_t)bs * 64 + lane * 2);
    *(float2*)(g_hmsg + (size_t)w * 64 + lane * 2) = v;
}

// ---------------- kernel 3: fused 3-layer LSTM (fp16 m16n8k16 mma, N-split) ----------------
__global__ __launch_bounds__(256, 2) void lstm_kernel(
    const float* __restrict__ feature,
    const float* __restrict__ h0, const float* __restrict__ c0,
    const float* __restrict__ bih0, const float* __restrict__ bhh0,
    const float* __restrict__ bih1, const float* __restrict__ bhh1,
    const float* __restrict__ bih2, const float* __restrict__ bhh2,
    float* __restrict__ out, int n)
{
    extern __shared__ char smem[];
    unsigned* Xw = (unsigned*)(smem + A_OFF);       // A as 32-bit words (2 halves each)
    float* bsum = (float*)(smem + BSUM_OFF);
    unsigned* Hst = (unsigned*)(smem + HST_OFF);    // pass-0 h stash, stride 17 words
    float* Csf = (float*)(smem + CS_OFF);           // c0 slice, stride 36 floats
    const uint32_t sbase = smem_u32(smem);

    const int tid = threadIdx.x;
    const int lane = tid & 31;
    const int warp = tid >> 5;
    const int wm = warp >> 1, wn = warp & 1;
    const int gid = lane >> 2, tig = lane & 3;
    const int m0w = wm * 32;
    const int m0 = blockIdx.x * 128;

    // staging role: thread -> (row, 32B half of 64B row)
    const int rp = tid >> 1;
    const int part = tid & 1;
    const int gP0 = (rp >> 5) * 64 + (rp & 31);     // global W row for pass 0
    const uint32_t bdst_local = (uint32_t)(rp * 80 + part * 32);
    const bool rowvalid = (m0 + rp) < n;
    const uint32_t cdst = sbase + CS_OFF + (uint32_t)(rp * 144 + part * 64);

    const float* bihA[3] = {bih0, bih1, bih2};
    const float* bhhA[3] = {bhh0, bhh1, bhh2};
    const size_t nd = (size_t)n * 64;
    float* out_hs = out + nd;
    float* out_cs = out + 4 * nd;

    // ---- hoisted prologue: stage (l=0,p=0) chunks 0,1 (+ c0 slice into group 0) ----
    {
        const __half* s0 = g_w16 + (size_t)gP0 * 128 + part * 16;
        uint32_t d0 = sbase + B_OFF + bdst_local;
        cp16(d0, s0); cp16(d0 + 16, s0 + 8);
        if (rowvalid) {
            const float* csrc = c0 + (size_t)(m0 + rp) * 64 + part * 16;   // l=0, p=0
            #pragma unroll
            for (int q = 0; q < 4; q++) cp16(cdst + q * 16, csrc + q * 4);
        }
        cp_commit();
        const __half* s1 = s0 + 32;
        uint32_t d1 = sbase + B_OFF + BBUF_SZ + bdst_local;
        cp16(d1, s1); cp16(d1 + 16, s1 + 8);
        cp_commit();
    }

    // ---- stage A for layer 0: [hmsg | feature | h0[0]], K=192, fp16 ----
    #pragma unroll 4
    for (int i = 0; i < 24; i++) {
        int idx = tid + (i << 8);
        int m = idx / 48, k4 = idx - m * 48;
        int node = m0 + m;
        float4 v = make_float4(0.f, 0.f, 0.f, 0.f);
        if (node < n) {
            size_t off = (size_t)node * 64;
            if (k4 < 16)      v = *(const float4*)(g_hmsg + off + k4 * 4);
            else if (k4 < 32) v = *(const float4*)(feature + off + (k4 - 16) * 4);
            else              v = *(const float4*)(h0 + off + (k4 - 32) * 4);
        }
        uint2 t;
        t.x = h2u(__floats2half2_rn(v.x, v.y));
        t.y = h2u(__floats2half2_rn(v.z, v.w));
        *(uint2*)(&Xw[m * 100 + k4 * 2]) = t;
    }

    for (int l = 0; l < 3; l++) {
        bsum[tid] = bihA[l][tid] + bhhA[l][tid];
        const int ncg = (l == 0) ? 6 : 4;

        for (int p = 0; p < 2; p++) {
            const int grow = gP0 + p * 32;

            if (!(l == 0 && p == 0)) {
                #pragma unroll 1
                for (int c = 0; c < 2; c++) {
                    const __half* wp; int rs, ko;
                    if (l == 0) { wp = g_w16 + c_woff[0]; rs = 128; ko = c * 32; }
                    else {
                        int reg = (c < 2) ? (2 * l) : (2 * l + 1);
                        wp = g_w16 + c_woff[reg]; rs = 64; ko = (c & 1) * 32;
                    }
                    const __half* src = wp + (size_t)grow * rs + ko + part * 16;
                    uint32_t dst = sbase + B_OFF + (c % 3) * BBUF_SZ + bdst_local;
                    cp16(dst, src); cp16(dst + 16, src + 8);
                    if (c == 0 && rowvalid) {   // piggyback this pass's c0 slice
                        const float* csrc = c0 + (size_t)l * nd + (size_t)(m0 + rp) * 64
                                          + p * 32 + part * 16;
                        #pragma unroll
                        for (int q = 0; q < 4; q++) cp16(cdst + q * 16, csrc + q * 4);
                    }
                    cp_commit();
                }
            }

            float acc[2][8][4];
            #pragma unroll
            for (int mf = 0; mf < 2; mf++)
                #pragma unroll
                for (int f = 0; f < 8; f++)
                    #pragma unroll
                    for (int q = 0; q < 4; q++) acc[mf][f][q] = 0.f;

            #pragma unroll 1
            for (int c = 0; c < ncg; c++) {
                if (c < ncg - 1) cp_wait1(); else cp_wait0();
                __syncthreads();

                const unsigned* Bw = (const unsigned*)(smem + B_OFF + (c % 3) * BBUF_SZ);
                const int kw = c * 16;                 // chunk base in words (32 halves)
                #pragma unroll
                for (int ks = 0; ks < 2; ks++) {
                    const int w0 = kw + ks * 8 + tig;
                    unsigned a[2][4];
                    #pragma unroll
                    for (int mf = 0; mf < 2; mf++) {
                        int r = m0w + mf * 16 + gid;
                        a[mf][0] = Xw[r * 100 + w0];
                        a[mf][1] = Xw[(r + 8) * 100 + w0];
                        a[mf][2] = Xw[r * 100 + w0 + 4];
                        a[mf][3] = Xw[(r + 8) * 100 + w0 + 4];
                    }
                    const int bw0 = ks * 8 + tig;
                    #pragma unroll
                    for (int f = 0; f < 8; f++) {
                        int nc = (f >> 1) * 32 + wn * 16 + (f & 1) * 8 + gid;
                        unsigned b0 = Bw[nc * 20 + bw0];
                        unsigned b1 = Bw[nc * 20 + bw0 + 4];
                        mma16(acc[0][f], a[0], b0, b1);
                        mma16(acc[1][f], a[1], b0, b1);
                    }
                }
                // stage chunk c+2 into ring buffer (c+2)%3 — retired at this chunk's barrier
                int c2 = c + 2;
                if (c2 < ncg) {
                    const __half* wp; int rs, ko;
                    if (l == 0) {
                        if (c2 < 4) { wp = g_w16 + c_woff[0]; rs = 128; ko = c2 * 32; }
                        else        { wp = g_w16 + c_woff[1]; rs = 64;  ko = (c2 - 4) * 32; }
                    } else {
                        int reg = (c2 < 2) ? (2 * l) : (2 * l + 1);
                        wp = g_w16 + c_woff[reg]; rs = 64; ko = (c2 & 1) * 32;
                    }
                    const __half* src = wp + (size_t)grow * rs + ko + part * 16;
                    uint32_t dst = sbase + B_OFF + (c2 % 3) * BBUF_SZ + bdst_local;
                    cp16(dst, src); cp16(dst + 16, src + 8);
                    cp_commit();
                }
            }
            __syncthreads();   // all MMAs + c0 prefetch visible before epilogue

            // ---------------- epilogue for this pass ----------------
            {
                const float* h0n = h0 + (size_t)(l + 1) * nd;
                float* hs_l = out_hs + (size_t)l * nd;
                float* cs_l = out_cs + (size_t)l * nd;

                #pragma unroll
                for (int mf = 0; mf < 2; mf++)
                    #pragma unroll
                    for (int jf = 0; jf < 2; jf++) {
                        const int d0 = p * 32 + wn * 16 + jf * 8 + 2 * tig;
                        const int dl = wn * 16 + jf * 8 + 2 * tig;     // col within pass slice
                        const int sw = wn * 8 + jf * 4 + tig;          // stash col word
                        #pragma unroll
                        for (int rh = 0; rh < 2; rh++) {
                            const int row = m0w + mf * 16 + gid + rh * 8;
                            const int node = m0 + row;
                            const bool valid = node < n;
                            const size_t noff = (size_t)node * 64;
                            float2 cp2 = *(const float2*)&Csf[row * 36 + dl];   // smem c0
                            float hv[2], cv[2];
                            #pragma unroll
                            for (int q = 0; q < 2; q++) {
                                const int pp = rh * 2 + q;
                                const int d = d0 + q;
                                float iv = acc[mf][0 + jf][pp] + bsum[d];
                                float fv = acc[mf][2 + jf][pp] + bsum[64 + d];
                                float gv = acc[mf][4 + jf][pp] + bsum[128 + d];
                                float ov = acc[mf][6 + jf][pp] + bsum[192 + d];
                                float cprev = q ? cp2.y : cp2.x;
                                float cn = fsig(fv) * cprev + fsig(iv) * ftanh(gv);
                                hv[q] = fsig(ov) * ftanh(cn);
                                cv[q] = cn;
                            }
                            if (valid) {
                                *(float2*)(hs_l + noff + d0) = make_float2(hv[0], hv[1]);
                                *(float2*)(cs_l + noff + d0) = make_float2(cv[0], cv[1]);
                                if (l == 2) *(float2*)(out + noff + d0) = make_float2(hv[0], hv[1]);
                            }
                            if (l < 2) {
                                unsigned hp16 = h2u(__floats2half2_rn(hv[0], hv[1]));
                                if (p == 0) {
                                    Hst[row * 17 + sw] = hp16;     // same-thread read in pass 1
                                } else {
                                    // pass-1 cols: own h + h0[l+1]
                                    Xw[row * 100 + (d0 >> 1)] = hp16;
                                    float2 hh = make_float2(0.f, 0.f);
                                    if (valid) hh = *(const float2*)(h0n + noff + d0);
                                    Xw[row * 100 + 32 + (d0 >> 1)] = h2u(__floats2half2_rn(hh.x, hh.y));
                                    // pass-0 cols: h from stash (fp16 already), h0 from global
                                    const int dp = d0 - 32;
                                    Xw[row * 100 + (dp >> 1)] = Hst[row * 17 + sw];
                                    float2 h2v = make_float2(0.f, 0.f);
                                    if (valid) h2v = *(const float2*)(h0n + noff + dp);
                                    Xw[row * 100 + 32 + (dp >> 1)] = h2u(__floats2half2_rn(h2v.x, h2v.y));
                                }
                            }
                        }
                    }
                __syncthreads();   // Xw/Cs reuse safe for next pass/layer
            }
        }
    }
}

// ---------------- launch ----------------
extern "C" void kernel_launch(void* const* d_in, const int* in_sizes, int n_in,
                              void* d_out, int out_size) {
    const float* feature = (const float*)d_in[0];
    const int* src       = (const int*)d_in[1];
    const float* h0      = (const float*)d_in[2];
    const float* c0      = (const float*)d_in[3];
    const float* wih0    = (const float*)d_in[4];
    const float* whh0    = (const float*)d_in[5];
    const float* bih0    = (const float*)d_in[6];
    const float* bhh0    = (const float*)d_in[7];
    const float* wih1    = (const float*)d_in[8];
    const float* whh1    = (const float*)d_in[9];
    const float* bih1    = (const float*)d_in[10];
    const float* bhh1    = (const float*)d_in[11];
    const float* wih2    = (const float*)d_in[12];
    const float* whh2    = (const float*)d_in[13];
    const float* bih2    = (const float*)d_in[14];
    const float* bhh2    = (const float*)d_in[15];
    float* out = (float*)d_out;

    int n = in_sizes[0] / 64;

    cudaFuncSetAttribute(lstm_kernel, cudaFuncAttributeMaxDynamicSharedMemorySize, SMEM_BYTES);

    wconv_kernel<<<224, 256>>>(wih0, whh0, wih1, whh1, wih2, whh2);

    int nblocks = (n * 16 + 255) / 256;
    norm2_kernel<<<nblocks, 256>>>(feature, n);
    int wblocks = (n + 7) / 8;
    gather_kernel<<<wblocks, 256>>>(feature, src, n);

    int lblocks = (n + 127) / 128;
    lstm_kernel<<<lblocks, 256, SMEM_BYTES>>>(
        feature, h0, c0,
        bih0, bhh0, bih1, bhh1, bih2, bhh2,
        out, n);
}